// round 14
// baseline (speedup 1.0000x reference)
#include <cuda_runtime.h>
#include <cuda_bf16.h>
#include <cstdint>

#define N_NODES 50000
#define N_EDGES 600000
#define D 128

#define SCAN_BT 256
#define SCAN_NB ((N_NODES + SCAN_BT - 1) / SCAN_BT)   // 196

// GEMM tile: 128 rows x 128 cols per block, 256 thr = 8 warps (4 m-pairs x 2 n)
#define GBM 128
#define GBN 128
#define NCHUNK 16                 // 256 K / 16 per chunk

// Scratch (__device__ globals; no allocation allowed)
__device__ float g_agg[N_NODES * D];
__device__ int   g_cnt[N_NODES];        // zeroed by gather after use each call
__device__ int   g_offs[N_NODES];
__device__ int   g_cursor[N_NODES];
__device__ unsigned long long g_scanstate[SCAN_NB];  // zeroed by hist_init each call
__device__ int2  g_sedge[N_EDGES];      // (src, weight-bits) sorted by dst
// W pre-packed as bf16 hi/lo words in mma-fragment order
__device__ __align__(16) uint32_t g_Wbh[NCHUNK * 1024];
__device__ __align__(16) uint32_t g_Wbl[NCHUNK * 1024];

// ---- index dtype detection (values < 50000; int64 LE => odd words zero) ----
__device__ __forceinline__ bool idx_is64(const int* p) {
    return ((p[1] | p[3] | p[5] | p[7]) == 0);
}
__device__ __forceinline__ int edge_idx(const int* p, bool is64, int e) {
    return is64 ? (int)((const long long*)p)[e] : p[e];
}

// ---- bf16 2-term split of a float pair, packed as bf16x2 words ----
__device__ __forceinline__ void splitpack2(float x0, float x1,
                                           uint32_t& h, uint32_t& l) {
    float h0 = __bfloat162float(__float2bfloat16_rn(x0));
    float h1 = __bfloat162float(__float2bfloat16_rn(x1));
    asm("cvt.rn.bf16x2.f32 %0, %1, %2;" : "=r"(h) : "f"(h1), "f"(h0));
    asm("cvt.rn.bf16x2.f32 %0, %1, %2;" : "=r"(l) : "f"(x1 - h1), "f"(x0 - h0));
}

// ---------------------------------------------------------------------------
// Fused hist + W-pack + scan-state reset
// ---------------------------------------------------------------------------
__global__ void hist_init_kernel(const float* __restrict__ W,
                                 const int* __restrict__ dst) {
    int idx = blockIdx.x * blockDim.x + threadIdx.x;
    if (idx < NCHUNK * 1024) {
        int chunk = idx >> 10;
        int ww    = idx & 1023;
        int tigr  = ww >> 8;
        int n     = (ww >> 1) & 127;
        int which = ww & 1;
        int kb    = chunk * 16 + tigr * 2 + which * 8;
        float x0 = W[n * 2 * D + kb];
        float x1 = W[n * 2 * D + kb + 1];
        uint32_t h, l;
        splitpack2(x0, x1, h, l);
        g_Wbh[idx] = h;
        g_Wbl[idx] = l;
    }
    if (idx < SCAN_NB) g_scanstate[idx] = 0ULL;
    if (idx < N_EDGES) {
        bool is64 = idx_is64(dst);
        atomicAdd(&g_cnt[edge_idx(dst, is64, idx)], 1);
    }
}

// ---------------------------------------------------------------------------
// Single-pass exclusive scan with decoupled lookback.
// g_scanstate[b] = (flag<<32) | value; flag 1=aggregate-only, 2=inclusive.
// Warp 0 of each block publishes + does warp-parallel lookback (32/step).
// ---------------------------------------------------------------------------
__global__ void scan_onepass() {
    __shared__ int sh[SCAN_BT];
    __shared__ int s_base;
    int t = threadIdx.x;
    int b = blockIdx.x;
    int i = b * SCAN_BT + t;
    int v = (i < N_NODES) ? g_cnt[i] : 0;
    sh[t] = v;
    __syncthreads();
    #pragma unroll
    for (int off = 1; off < SCAN_BT; off <<= 1) {
        int u = (t >= off) ? sh[t - off] : 0;
        __syncthreads();
        sh[t] += u;
        __syncthreads();
    }
    int excl_self = sh[t] - v;
    int total = sh[SCAN_BT - 1];

    if (t < 32) {
        if (b == 0) {
            if (t == 0) {
                atomicExch(&g_scanstate[0], (2ULL << 32) | (unsigned int)total);
                s_base = 0;
            }
        } else {
            if (t == 0)
                atomicExch(&g_scanstate[b], (1ULL << 32) | (unsigned int)total);
            int base = 0;
            int winEnd = b;          // window covers [winEnd-32, winEnd), lane t -> winEnd-1-t
            for (;;) {
                int j = winEnd - 1 - t;
                unsigned long long st;
                if (j >= 0) {
                    do { st = atomicAdd(&g_scanstate[j], 0ULL); }
                    while ((int)(st >> 32) == 0);
                } else {
                    st = (2ULL << 32);    // virtual inclusive 0 before block 0
                }
                int flag = (int)(st >> 32);
                int val  = (int)(st & 0xffffffffULL);
                unsigned incl = __ballot_sync(0xffffffffu, flag == 2);
                if (incl) {
                    int firstIncl = __ffs(incl) - 1;    // closest inclusive going back
                    int contrib = (t <= firstIncl) ? val : 0;
                    #pragma unroll
                    for (int o = 16; o > 0; o >>= 1)
                        contrib += __shfl_down_sync(0xffffffffu, contrib, o);
                    if (t == 0) base += contrib;
                    break;
                } else {
                    int contrib = val;
                    #pragma unroll
                    for (int o = 16; o > 0; o >>= 1)
                        contrib += __shfl_down_sync(0xffffffffu, contrib, o);
                    if (t == 0) base += contrib;
                    winEnd -= 32;
                }
            }
            if (t == 0) {
                atomicExch(&g_scanstate[b], (2ULL << 32) | (unsigned int)(base + total));
                s_base = base;
            }
        }
    }
    __syncthreads();
    if (i < N_NODES) {
        int o = excl_self + s_base;
        g_offs[i] = o;
        g_cursor[i] = o;
    }
}

// ---------------------------------------------------------------------------
// Scatter: one packed 8B store per edge (src, weight-bits)
// ---------------------------------------------------------------------------
__global__ void scatter_ids_kernel(const float* __restrict__ ew,
                                   const int* __restrict__ src,
                                   const int* __restrict__ dst) {
    int e = blockIdx.x * blockDim.x + threadIdx.x;
    if (e >= N_EDGES) return;
    bool s64 = idx_is64(src);
    bool d64 = idx_is64(dst);
    int s = edge_idx(src, s64, e);
    int d = edge_idx(dst, d64, e);
    float wgt = ew[e];
    int pos = atomicAdd(&g_cursor[d], 1);
    g_sedge[pos] = make_int2(s, __float_as_int(wgt));
}

// Warp-per-node gather, unroll-4; zeroes g_cnt after use (next-call hist)
__global__ void gather_kernel(const float* __restrict__ nf) {
    int w = (blockIdx.x * blockDim.x + threadIdx.x) >> 5;
    int lane = threadIdx.x & 31;
    if (w >= N_NODES) return;
    int beg = g_offs[w];
    int deg = g_cnt[w];
    const float4* nf4 = (const float4*)nf;
    float4 acc = make_float4(0.f, 0.f, 0.f, 0.f);

    int i = 0;
    for (; i + 4 <= deg; i += 4) {
        int2 e0 = g_sedge[beg + i];
        int2 e1 = g_sedge[beg + i + 1];
        int2 e2 = g_sedge[beg + i + 2];
        int2 e3 = g_sedge[beg + i + 3];
        float w0 = __int_as_float(e0.y);
        float w1 = __int_as_float(e1.y);
        float w2 = __int_as_float(e2.y);
        float w3 = __int_as_float(e3.y);
        float4 v0 = nf4[e0.x * (D / 4) + lane];
        float4 v1 = nf4[e1.x * (D / 4) + lane];
        float4 v2 = nf4[e2.x * (D / 4) + lane];
        float4 v3 = nf4[e3.x * (D / 4) + lane];
        acc.x += v0.x * w0; acc.y += v0.y * w0; acc.z += v0.z * w0; acc.w += v0.w * w0;
        acc.x += v1.x * w1; acc.y += v1.y * w1; acc.z += v1.z * w1; acc.w += v1.w * w1;
        acc.x += v2.x * w2; acc.y += v2.y * w2; acc.z += v2.z * w2; acc.w += v2.w * w2;
        acc.x += v3.x * w3; acc.y += v3.y * w3; acc.z += v3.z * w3; acc.w += v3.w * w3;
    }
    for (; i < deg; i++) {
        int2 e0 = g_sedge[beg + i];
        float wt = __int_as_float(e0.y);
        float4 v = nf4[e0.x * (D / 4) + lane];
        acc.x += v.x * wt; acc.y += v.y * wt; acc.z += v.z * wt; acc.w += v.w * wt;
    }
    float inv = (deg > 0) ? (1.0f / (float)deg) : 0.0f;
    acc.x *= inv; acc.y *= inv; acc.z *= inv; acc.w *= inv;
    ((float4*)g_agg)[w * (D / 4) + lane] = acc;
    if (lane == 0) g_cnt[w] = 0;   // reset for next call's hist
}

// ---------------------------------------------------------------------------
// bf16-split MMA GEMM, GBM=128 (unchanged from Round 12)
// ---------------------------------------------------------------------------
__device__ __forceinline__ void mma_bf16(float* c, const uint32_t* a,
                                         uint32_t b0, uint32_t b1) {
    asm volatile(
        "mma.sync.aligned.m16n8k16.row.col.f32.bf16.bf16.f32 "
        "{%0,%1,%2,%3}, {%4,%5,%6,%7}, {%8,%9}, {%0,%1,%2,%3};"
        : "+f"(c[0]), "+f"(c[1]), "+f"(c[2]), "+f"(c[3])
        : "r"(a[0]), "r"(a[1]), "r"(a[2]), "r"(a[3]), "r"(b0), "r"(b1));
}

__global__ __launch_bounds__(256, 2)
void gemm_bf16_kernel(const float* __restrict__ nf,
                      const float* __restrict__ bias,
                      float* __restrict__ out) {
    __shared__ __align__(16) uint32_t Ah[2][1024];
    __shared__ __align__(16) uint32_t Al[2][1024];
    __shared__ __align__(16) uint32_t Bh[2][4][264];
    __shared__ __align__(16) uint32_t Bl[2][4][264];

    int tx   = threadIdx.x;
    int w    = tx >> 5;
    int lane = tx & 31;
    int g    = lane >> 2;
    int tig  = lane & 3;
    int mwg  = w >> 1;
    int nw   = (w & 1) * 64;
    int n0   = blockIdx.x * GBM;

    float c[2][8][4];
    #pragma unroll
    for (int mt = 0; mt < 2; mt++)
        #pragma unroll
        for (int t = 0; t < 8; t++)
            #pragma unroll
            for (int i = 0; i < 4; i++) c[mt][t][i] = 0.f;

    int am[2], aq[2], ad0[2], ad1[2], anode[2];
    #pragma unroll
    for (int r = 0; r < 2; r++) {
        int f4 = tx + r * 256;
        am[r] = f4 >> 2;
        aq[r] = f4 & 3;
        int an = n0 + am[r];
        anode[r] = (an < N_NODES) ? an : 0;
        int ar = am[r] & 15, ag = ar & 7, ahalf = ar >> 3, amg = am[r] >> 4;
        int i0 = 2 * aq[r], i1 = 2 * aq[r] + 1;
        ad0[r] = amg * 128 + (4 * ag + (i0 & 3)) * 4 + ahalf + 2 * (i0 >> 2);
        ad1[r] = amg * 128 + (4 * ag + (i1 & 3)) * 4 + ahalf + 2 * (i1 >> 2);
    }

    const uint2* Wh2 = (const uint2*)g_Wbh;
    const uint2* Wl2 = (const uint2*)g_Wbl;
    int t0row = tx >> 7;
    int t0off = (2 * tx) & 255;

    #pragma unroll
    for (int r = 0; r < 2; r++) {
        float4 f = *(const float4*)(g_agg + (long long)anode[r] * D + aq[r] * 4);
        uint32_t h0, l0, h1, l1;
        splitpack2(f.x, f.y, h0, l0);
        splitpack2(f.z, f.w, h1, l1);
        Ah[0][ad0[r]] = h0; Al[0][ad0[r]] = l0;
        Ah[0][ad1[r]] = h1; Al[0][ad1[r]] = l1;
    }
    {
        uint2 bh0 = Wh2[tx], bh1 = Wh2[tx + 256];
        uint2 bl0 = Wl2[tx], bl1 = Wl2[tx + 256];
        *(uint2*)&Bh[0][t0row][t0off]     = bh0;
        *(uint2*)&Bh[0][t0row + 2][t0off] = bh1;
        *(uint2*)&Bl[0][t0row][t0off]     = bl0;
        *(uint2*)&Bl[0][t0row + 2][t0off] = bl1;
    }
    __syncthreads();

    for (int kt = 0; kt < NCHUNK; kt++) {
        int b = kt & 1;

        float4 pf[2];
        uint2 ph0, ph1, pl0, pl1;
        if (kt + 1 < NCHUNK) {
            int k0 = (kt + 1) * 16;
            const float* zb = (k0 < D) ? (g_agg + k0) : (nf + (k0 - D));
            #pragma unroll
            for (int r = 0; r < 2; r++)
                pf[r] = *(const float4*)(zb + (long long)anode[r] * D + aq[r] * 4);
            int cb = (kt + 1) * 512;
            ph0 = Wh2[cb + tx]; ph1 = Wh2[cb + tx + 256];
            pl0 = Wl2[cb + tx]; pl1 = Wl2[cb + tx + 256];
        }

        uint32_t ah[2][4], al[2][4];
        #pragma unroll
        for (int mt = 0; mt < 2; mt++) {
            uint4 h4 = *(const uint4*)&Ah[b][(2 * mwg + mt) * 128 + lane * 4];
            uint4 l4 = *(const uint4*)&Al[b][(2 * mwg + mt) * 128 + lane * 4];
            ah[mt][0] = h4.x; ah[mt][1] = h4.y; ah[mt][2] = h4.z; ah[mt][3] = h4.w;
            al[mt][0] = l4.x; al[mt][1] = l4.y; al[mt][2] = l4.z; al[mt][3] = l4.w;
        }
        #pragma unroll
        for (int t = 0; t < 8; t++) {
            int nn = nw + t * 8 + g;
            uint2 bh = *(const uint2*)&Bh[b][tig][nn * 2];
            uint2 bl = *(const uint2*)&Bl[b][tig][nn * 2];
            #pragma unroll
            for (int mt = 0; mt < 2; mt++) {
                mma_bf16(c[mt][t], ah[mt], bh.x, bh.y);
                mma_bf16(c[mt][t], al[mt], bh.x, bh.y);
                mma_bf16(c[mt][t], ah[mt], bl.x, bl.y);
            }
        }

        if (kt + 1 < NCHUNK) {
            int nb = b ^ 1;
            #pragma unroll
            for (int r = 0; r < 2; r++) {
                uint32_t h0, l0, h1, l1;
                splitpack2(pf[r].x, pf[r].y, h0, l0);
                splitpack2(pf[r].z, pf[r].w, h1, l1);
                Ah[nb][ad0[r]] = h0; Al[nb][ad0[r]] = l0;
                Ah[nb][ad1[r]] = h1; Al[nb][ad1[r]] = l1;
            }
            *(uint2*)&Bh[nb][t0row][t0off]     = ph0;
            *(uint2*)&Bh[nb][t0row + 2][t0off] = ph1;
            *(uint2*)&Bl[nb][t0row][t0off]     = pl0;
            *(uint2*)&Bl[nb][t0row + 2][t0off] = pl1;
        }
        __syncthreads();
    }

    #pragma unroll
    for (int mt = 0; mt < 2; mt++) {
        int r0 = n0 + mwg * 32 + mt * 16 + g;
        int r1 = r0 + 8;
        #pragma unroll
        for (int t = 0; t < 8; t++) {
            int col = nw + t * 8 + 2 * tig;
            float2 bv = *(const float2*)(bias + col);
            if (r0 < N_NODES) {
                float2 o0 = make_float2(c[mt][t][0] + bv.x, c[mt][t][1] + bv.y);
                *(float2*)(out + (long long)r0 * GBN + col) = o0;
            }
            if (r1 < N_NODES) {
                float2 o1 = make_float2(c[mt][t][2] + bv.x, c[mt][t][3] + bv.y);
                *(float2*)(out + (long long)r1 * GBN + col) = o1;
            }
        }
    }
}

// ---------------------------------------------------------------------------
extern "C" void kernel_launch(void* const* d_in, const int* in_sizes, int n_in,
                              void* d_out, int out_size) {
    const float* nf   = (const float*)d_in[0];
    const float* ew   = (const float*)d_in[1];
    const float* W    = (const float*)d_in[2];
    const float* bias = (const float*)d_in[3];
    const int* src    = (const int*)d_in[4];
    const int* dst    = (const int*)d_in[5];
    float* out        = (float*)d_out;

    hist_init_kernel<<<(N_EDGES + 255) / 256, 256>>>(W, dst);
    scan_onepass<<<SCAN_NB, SCAN_BT>>>();
    scatter_ids_kernel<<<(N_EDGES + 255) / 256, 256>>>(ew, src, dst);
    gather_kernel<<<(N_NODES * 32 + 255) / 256, 256>>>(nf);
    gemm_bf16_kernel<<<(N_NODES + GBM - 1) / GBM, 256>>>(nf, bias, out);
}